// round 2
// baseline (speedup 1.0000x reference)
#include <cuda_runtime.h>
#include <cuda_bf16.h>
#include <math.h>

// ---------------------------------------------------------------------------
// Problem constants
// ---------------------------------------------------------------------------
#define BB    4
#define SS    1020
#define DDIM  1024
#define HH    16
#define DH    64
#define LL    4
#define TPB_  17
#define FF    4096
#define NTOK  (BB * SS)          // 4080
#define NOBS  (BB * 960)         // 3840 rows for obs head
#define NACT  (BB * 60)          // 240 rows for ends head
#define VOBS_ 4096
#define VACT_ 16

// ---------------------------------------------------------------------------
// Static device scratch (no runtime allocation allowed)
// ---------------------------------------------------------------------------
__device__ float g_x   [NTOK * DDIM];
__device__ float g_h   [NTOK * DDIM];
__device__ float g_q   [NTOK * DDIM];
__device__ float g_k   [NTOK * DDIM];
__device__ float g_v   [NTOK * DDIM];
__device__ float g_o   [NTOK * DDIM];
__device__ float g_mid [NTOK * FF];
__device__ float g_t1  [NOBS * DDIM];
__device__ float g_t2  [NACT * DDIM];
__device__ int   g_obs_rows[NOBS];
__device__ int   g_act_rows[NACT];

// ---------------------------------------------------------------------------
// Embedding: x[b,s,:] = (is_obs ? emb_obs[tok] : emb_act[tok]) + pos_emb[s]
// ---------------------------------------------------------------------------
__global__ void embed_kernel(const int* __restrict__ tokens,
                             const float* __restrict__ pos_emb,
                             const float* __restrict__ emb_obs,
                             const float* __restrict__ emb_act,
                             float* __restrict__ x)
{
    int row = blockIdx.x;                 // 0..NTOK-1
    int s   = row % SS;
    int tok = tokens[row];
    bool is_obs = (s % TPB_) < (TPB_ - 1);
    const float* e = is_obs ? (emb_obs + (size_t)min(tok, VOBS_ - 1) * DDIM)
                            : (emb_act + (size_t)min(tok, VACT_ - 1) * DDIM);
    const float* pe = pos_emb + (size_t)s * DDIM;
    float* xo = x + (size_t)row * DDIM;
    for (int d = threadIdx.x; d < DDIM; d += blockDim.x)
        xo[d] = e[d] + pe[d];
}

// ---------------------------------------------------------------------------
// Block reduction (256 threads)
// ---------------------------------------------------------------------------
__device__ __forceinline__ float block_sum256(float v)
{
    __shared__ float sh[8];
    int lane = threadIdx.x & 31, w = threadIdx.x >> 5;
    #pragma unroll
    for (int o = 16; o > 0; o >>= 1) v += __shfl_xor_sync(0xffffffffu, v, o);
    if (lane == 0) sh[w] = v;
    __syncthreads();
    if (w == 0) {
        float t = (lane < 8) ? sh[lane] : 0.f;
        #pragma unroll
        for (int o = 4; o > 0; o >>= 1) t += __shfl_xor_sync(0xffffffffu, t, o);
        if (lane == 0) sh[0] = t;
    }
    __syncthreads();
    float r = sh[0];
    __syncthreads();
    return r;
}

// ---------------------------------------------------------------------------
// LayerNorm: one block (256 threads) per row, 4 elems/thread
// ---------------------------------------------------------------------------
__global__ void ln_kernel(const float* __restrict__ x,
                          const float* __restrict__ g,
                          const float* __restrict__ b,
                          float* __restrict__ out)
{
    int row = blockIdx.x;
    const float* xr = x + (size_t)row * DDIM;
    float* orow = out + (size_t)row * DDIM;
    int t = threadIdx.x;
    float v[4];
    float s = 0.f;
    #pragma unroll
    for (int i = 0; i < 4; ++i) { v[i] = xr[t + 256 * i]; s += v[i]; }
    float mean = block_sum256(s) * (1.f / (float)DDIM);
    float q = 0.f;
    #pragma unroll
    for (int i = 0; i < 4; ++i) { float d = v[i] - mean; q += d * d; }
    float var  = block_sum256(q) * (1.f / (float)DDIM);
    float rstd = rsqrtf(var + 1e-3f);
    #pragma unroll
    for (int i = 0; i < 4; ++i) {
        int idx = t + 256 * i;
        orow[idx] = (v[i] - mean) * rstd * g[idx] + b[idx];
    }
}

// ---------------------------------------------------------------------------
// Generic fp32 GEMM: C[M,N] = act(A[M,K] @ W[K,N] + bias) (+ resid)
// BM=128, BN=128, BK=8, 256 threads, 8x8 per-thread tile.
// rowmap (optional): A-row index for output row m (gather).
// ACT: 0 = none, 1 = exact GELU, 2 = ReLU
// ---------------------------------------------------------------------------
template<int ACT>
__global__ __launch_bounds__(256)
void gemm_kernel(const float* __restrict__ A, const float* __restrict__ W,
                 const float* __restrict__ bias, float* __restrict__ C,
                 const float* __restrict__ resid, const int* __restrict__ rowmap,
                 int M, int N, int K)
{
    __shared__ float As[8][128];
    __shared__ float Ws[8][128];

    int tid = threadIdx.x;
    int m0 = blockIdx.y * 128;
    int n0 = blockIdx.x * 128;
    int tx = tid & 15;   // n sub-tile
    int ty = tid >> 4;   // m sub-tile

    float acc[8][8];
    #pragma unroll
    for (int i = 0; i < 8; ++i)
        #pragma unroll
        for (int j = 0; j < 8; ++j) acc[i][j] = 0.f;

    // A tile loader: each thread loads one float4
    int arow = tid >> 1;               // 0..127
    int acol = (tid & 1) * 4;          // 0 or 4
    int am   = m0 + arow;
    int amap = -1;
    if (am < M) amap = rowmap ? rowmap[am] : am;
    const float* Aptr = (amap >= 0) ? (A + (size_t)amap * K + acol) : A;

    // W tile loader
    int wrow = tid >> 5;               // 0..7
    int wcol = (tid & 31) * 4;         // 0..124
    const float* Wptr = W + (size_t)wrow * N + n0 + wcol;

    for (int k0 = 0; k0 < K; k0 += 8) {
        float4 av = (amap >= 0) ? *(const float4*)Aptr : make_float4(0.f, 0.f, 0.f, 0.f);
        float4 wv = *(const float4*)Wptr;
        __syncthreads();
        As[acol + 0][arow] = av.x;
        As[acol + 1][arow] = av.y;
        As[acol + 2][arow] = av.z;
        As[acol + 3][arow] = av.w;
        *(float4*)&Ws[wrow][wcol] = wv;
        __syncthreads();
        #pragma unroll
        for (int kk = 0; kk < 8; ++kk) {
            float a[8], w[8];
            #pragma unroll
            for (int i = 0; i < 8; ++i) a[i] = As[kk][ty + 16 * i];
            #pragma unroll
            for (int j = 0; j < 8; ++j) w[j] = Ws[kk][tx + 16 * j];
            #pragma unroll
            for (int i = 0; i < 8; ++i)
                #pragma unroll
                for (int j = 0; j < 8; ++j)
                    acc[i][j] = fmaf(a[i], w[j], acc[i][j]);
        }
        Aptr += 8;
        Wptr += (size_t)8 * N;
    }

    #pragma unroll
    for (int i = 0; i < 8; ++i) {
        int m = m0 + ty + 16 * i;
        if (m >= M) continue;
        #pragma unroll
        for (int j = 0; j < 8; ++j) {
            int n = n0 + tx + 16 * j;
            float vv = acc[i][j] + bias[n];
            if (ACT == 1) vv = 0.5f * vv * (1.0f + erff(vv * 0.70710678118654752f));
            if (ACT == 2) vv = fmaxf(vv, 0.f);
            if (resid) vv += resid[(size_t)m * N + n];
            C[(size_t)m * N + n] = vv;
        }
    }
}

// ---------------------------------------------------------------------------
// Fused causal attention (flash-style online softmax).
// grid: (num q-tiles of 64, B*H), block: 64 threads (1 thread = 1 query row)
// q/k/v layout: [B*S, D] with head h at column h*DH.
// ---------------------------------------------------------------------------
__global__ void attn_kernel(const float* __restrict__ q,
                            const float* __restrict__ k,
                            const float* __restrict__ v,
                            float* __restrict__ o)
{
    int bh = blockIdx.y;            // 0..B*H-1
    int b = bh >> 4, h = bh & 15;
    int qt = blockIdx.x;
    int tid = threadIdx.x;          // 0..63
    int i = qt * 64 + tid;
    bool valid = i < SS;
    int irow = valid ? i : SS - 1;
    size_t base = (size_t)b * SS * DDIM + (size_t)h * DH;

    float qreg[64];
    {
        const float4* q4 = (const float4*)(q + base + (size_t)irow * DDIM);
        #pragma unroll
        for (int d4 = 0; d4 < 16; ++d4) {
            float4 t = q4[d4];
            qreg[4 * d4 + 0] = t.x; qreg[4 * d4 + 1] = t.y;
            qreg[4 * d4 + 2] = t.z; qreg[4 * d4 + 3] = t.w;
        }
    }

    __shared__ float4 Ksh[64][16];
    __shared__ float4 Vsh[64][16];

    float oacc[64];
    #pragma unroll
    for (int d = 0; d < 64; ++d) oacc[d] = 0.f;
    float m = -1e30f, l = 0.f;
    const float scale = 0.125f;     // 1/sqrt(64)

    for (int kt = 0; kt <= qt; ++kt) {
        int j0 = kt * 64;
        int nk = min(64, SS - j0);
        __syncthreads();
        #pragma unroll
        for (int it = 0; it < 16; ++it) {
            int idx = it * 64 + tid;
            int j = idx >> 4, d4 = idx & 15;
            if (j < nk) {
                Ksh[j][d4] = *(const float4*)(k + base + (size_t)(j0 + j) * DDIM + 4 * d4);
                Vsh[j][d4] = *(const float4*)(v + base + (size_t)(j0 + j) * DDIM + 4 * d4);
            }
        }
        __syncthreads();
        if (valid) {
            const float* Ks = (const float*)Ksh;
            const float* Vs = (const float*)Vsh;
            int jend = min(nk, i - j0 + 1);
            for (int j = 0; j < jend; ++j) {
                const float* kr = Ks + j * 64;
                float s = 0.f;
                #pragma unroll
                for (int d = 0; d < 64; ++d) s = fmaf(qreg[d], kr[d], s);
                s *= scale;
                const float* vr = Vs + j * 64;
                if (s > m) {
                    float c = __expf(m - s);
                    l = l * c + 1.f;
                    #pragma unroll
                    for (int d = 0; d < 64; ++d) oacc[d] = fmaf(oacc[d], c, vr[d]);
                    m = s;
                } else {
                    float p = __expf(s - m);
                    l += p;
                    #pragma unroll
                    for (int d = 0; d < 64; ++d) oacc[d] = fmaf(p, vr[d], oacc[d]);
                }
            }
        }
    }

    if (valid) {
        float inv = 1.f / l;
        float* orow = o + base + (size_t)irow * DDIM;
        #pragma unroll
        for (int d = 0; d < 64; ++d) orow[d] = oacc[d] * inv;
    }
}

// ---------------------------------------------------------------------------
// Build gather indices for the two heads
// obs rows: p % 17 != 15 (16/block of 17); act rows: p % 17 == 16
// ---------------------------------------------------------------------------
__global__ void build_idx_kernel()
{
    int t = blockIdx.x * blockDim.x + threadIdx.x;
    if (t < NOBS) {
        int b = t / 960, j = t % 960;
        int blk = j / 16, r = j % 16;
        int p = blk * TPB_ + (r < 15 ? r : 16);
        g_obs_rows[t] = b * SS + p;
    }
    if (t < NACT) {
        int b = t / 60, blk = t % 60;
        g_act_rows[t] = b * SS + blk * TPB_ + (TPB_ - 1);
    }
}

// ---------------------------------------------------------------------------
// Tiny N=2 head: logits_ends = t2 @ he2 + be2
// ---------------------------------------------------------------------------
__global__ void head_ends_kernel(const float* __restrict__ t2,
                                 const float* __restrict__ w,
                                 const float* __restrict__ bias,
                                 float* __restrict__ out)
{
    int r = blockIdx.x;
    int tid = threadIdx.x;  // 128
    const float* a = t2 + (size_t)r * DDIM;
    float s0 = 0.f, s1 = 0.f;
    for (int kk = tid; kk < DDIM; kk += 128) {
        float av = a[kk];
        s0 = fmaf(av, w[kk * 2 + 0], s0);
        s1 = fmaf(av, w[kk * 2 + 1], s1);
    }
    __shared__ float red[128];
    red[tid] = s0; __syncthreads();
    for (int st = 64; st > 0; st >>= 1) { if (tid < st) red[tid] += red[tid + st]; __syncthreads(); }
    if (tid == 0) out[r * 2 + 0] = red[0] + bias[0];
    __syncthreads();
    red[tid] = s1; __syncthreads();
    for (int st = 64; st > 0; st >>= 1) { if (tid < st) red[tid] += red[tid + st]; __syncthreads(); }
    if (tid == 0) out[r * 2 + 1] = red[0] + bias[1];
}

// ---------------------------------------------------------------------------
// Launch
// ---------------------------------------------------------------------------
extern "C" void kernel_launch(void* const* d_in, const int* in_sizes, int n_in,
                              void* d_out, int out_size)
{
    const int*   tokens  = (const int*)  d_in[0];
    const float* pos_emb = (const float*)d_in[1];
    const float* emb_obs = (const float*)d_in[2];
    const float* emb_act = (const float*)d_in[3];
    const float* ln1_g   = (const float*)d_in[4];
    const float* ln1_b   = (const float*)d_in[5];
    const float* wq      = (const float*)d_in[6];
    const float* bq      = (const float*)d_in[7];
    const float* wk      = (const float*)d_in[8];
    const float* bk      = (const float*)d_in[9];
    const float* wv      = (const float*)d_in[10];
    const float* bv      = (const float*)d_in[11];
    const float* wo      = (const float*)d_in[12];
    const float* bo      = (const float*)d_in[13];
    const float* ln2_g   = (const float*)d_in[14];
    const float* ln2_b   = (const float*)d_in[15];
    const float* w1      = (const float*)d_in[16];
    const float* b1      = (const float*)d_in[17];
    const float* w2      = (const float*)d_in[18];
    const float* b2      = (const float*)d_in[19];
    const float* lnf_g   = (const float*)d_in[20];
    const float* lnf_b   = (const float*)d_in[21];
    const float* ho1     = (const float*)d_in[22];
    const float* bo1     = (const float*)d_in[23];
    const float* ho2     = (const float*)d_in[24];
    const float* bo2     = (const float*)d_in[25];
    const float* he1     = (const float*)d_in[26];
    const float* be1     = (const float*)d_in[27];
    const float* he2     = (const float*)d_in[28];
    const float* be2     = (const float*)d_in[29];
    float* out = (float*)d_out;

    float *x, *h, *q, *k, *v, *o, *mid, *t1, *t2;
    int *obsr, *actr;
    cudaGetSymbolAddress((void**)&x,   g_x);
    cudaGetSymbolAddress((void**)&h,   g_h);
    cudaGetSymbolAddress((void**)&q,   g_q);
    cudaGetSymbolAddress((void**)&k,   g_k);
    cudaGetSymbolAddress((void**)&v,   g_v);
    cudaGetSymbolAddress((void**)&o,   g_o);
    cudaGetSymbolAddress((void**)&mid, g_mid);
    cudaGetSymbolAddress((void**)&t1,  g_t1);
    cudaGetSymbolAddress((void**)&t2,  g_t2);
    cudaGetSymbolAddress((void**)&obsr, g_obs_rows);
    cudaGetSymbolAddress((void**)&actr, g_act_rows);

    const int MB = (NTOK + 127) / 128;   // 32
    dim3 gD(DDIM / 128, MB);             // (8, 32)
    dim3 gF(FF / 128, MB);               // (32, 32)

    embed_kernel<<<NTOK, 256>>>(tokens, pos_emb, emb_obs, emb_act, x);

    for (int l = 0; l < LL; ++l) {
        size_t wofs = (size_t)l * DDIM * DDIM;
        ln_kernel<<<NTOK, 256>>>(x, ln1_g + l * DDIM, ln1_b + l * DDIM, h);
        gemm_kernel<0><<<gD, 256>>>(h, wq + wofs, bq + l * DDIM, q, nullptr, nullptr, NTOK, DDIM, DDIM);
        gemm_kernel<0><<<gD, 256>>>(h, wk + wofs, bk + l * DDIM, k, nullptr, nullptr, NTOK, DDIM, DDIM);
        gemm_kernel<0><<<gD, 256>>>(h, wv + wofs, bv + l * DDIM, v, nullptr, nullptr, NTOK, DDIM, DDIM);
        attn_kernel<<<dim3((SS + 63) / 64, BB * HH), 64>>>(q, k, v, o);
        gemm_kernel<0><<<gD, 256>>>(o, wo + wofs, bo + l * DDIM, x, x, nullptr, NTOK, DDIM, DDIM);
        ln_kernel<<<NTOK, 256>>>(x, ln2_g + l * DDIM, ln2_b + l * DDIM, h);
        gemm_kernel<1><<<gF, 256>>>(h, w1 + (size_t)l * DDIM * FF, b1 + (size_t)l * FF, mid,
                                    nullptr, nullptr, NTOK, FF, DDIM);
        gemm_kernel<0><<<gD, 256>>>(mid, w2 + (size_t)l * FF * DDIM, b2 + l * DDIM, x,
                                    x, nullptr, NTOK, DDIM, FF);
    }

    ln_kernel<<<NTOK, 256>>>(x, lnf_g, lnf_b, h);
    build_idx_kernel<<<(NOBS + 255) / 256, 256>>>();

    // obs head: gather -> relu(x@ho1+bo1) -> @ho2+bo2 -> out[0 : NOBS*4096)
    gemm_kernel<2><<<dim3(DDIM / 128, (NOBS + 127) / 128), 256>>>(
        h, ho1, bo1, t1, nullptr, obsr, NOBS, DDIM, DDIM);
    gemm_kernel<0><<<dim3(VOBS_ / 128, (NOBS + 127) / 128), 256>>>(
        t1, ho2, bo2, out, nullptr, nullptr, NOBS, VOBS_, DDIM);

    // ends head: gather -> relu(x@he1+be1) -> @he2+be2 -> out[NOBS*4096 : ...)
    gemm_kernel<2><<<dim3(DDIM / 128, (NACT + 127) / 128), 256>>>(
        h, he1, be1, t2, nullptr, actr, NACT, DDIM, DDIM);
    head_ends_kernel<<<NACT, 128>>>(t2, he2, be2, out + (size_t)NOBS * VOBS_);
}

// round 4
// speedup vs baseline: 2.4987x; 2.4987x over previous
#include <cuda_runtime.h>
#include <cuda_bf16.h>
#include <math.h>
#include <stdint.h>

typedef __nv_bfloat16 bf16;

#define BB 4
#define SS 1020
#define DDIM 1024
#define HH 16
#define DH 64
#define LL 4
#define TPB_ 17
#define FF 4096
#define NTOK (BB*SS)
#define NOBS (BB*960)
#define NACT (BB*60)
#define VOBS_ 4096
#define VACT_ 16

// ---------------- static scratch ----------------
__device__ __align__(256) float g_x[NTOK*DDIM];
__device__ __align__(256) float g_qkv[NTOK*3*DDIM];
__device__ __align__(256) float g_t2[NACT*DDIM];
__device__ __align__(256) bf16 g_h_hi[NTOK*DDIM];
__device__ __align__(256) bf16 g_h_lo[NTOK*DDIM];
__device__ __align__(256) bf16 g_o_hi[NTOK*DDIM];
__device__ __align__(256) bf16 g_o_lo[NTOK*DDIM];
__device__ __align__(256) bf16 g_mid_hi[NTOK*FF];
__device__ __align__(256) bf16 g_mid_lo[NTOK*FF];
__device__ __align__(256) bf16 g_t1_hi[NOBS*DDIM];
__device__ __align__(256) bf16 g_t1_lo[NOBS*DDIM];
__device__ float g_bqkv[LL*3*DDIM];
__device__ int g_obs_rows[NOBS];
__device__ int g_act_rows[NACT];

#define WQKV_OFF 0
#define WO_OFF  (WQKV_OFF + LL*3*DDIM*DDIM)
#define W1_OFF  (WO_OFF + LL*DDIM*DDIM)
#define W2_OFF  (W1_OFF + LL*FF*DDIM)
#define HO1_OFF (W2_OFF + LL*DDIM*FF)
#define HO2_OFF (HO1_OFF + DDIM*DDIM)
#define HE1_OFF (HO2_OFF + VOBS_*DDIM)
#define WT_TOT  (HE1_OFF + DDIM*DDIM)
__device__ __align__(256) bf16 g_wt_hi[WT_TOT];
__device__ __align__(256) bf16 g_wt_lo[WT_TOT];

// ---------------- PTX helpers (sm_80 baseline features only) ----------------
__device__ __forceinline__ uint32_t s2u(const void* p){ return (uint32_t)__cvta_generic_to_shared(p); }
__device__ __forceinline__ void cp16(uint32_t d, const void* s){
    asm volatile("cp.async.cg.shared.global [%0], [%1], 16;\n"::"r"(d),"l"(s));
}
#define CP_COMMIT() asm volatile("cp.async.commit_group;\n":::"memory")
#define CP_WAIT1()  asm volatile("cp.async.wait_group 1;\n":::"memory")

#define SWZ(o) ((o) ^ (((o)>>3)&0x70))

#define LDM4(r0,r1,r2,r3,a) \
    asm volatile("ldmatrix.sync.aligned.m8n8.x4.shared.b16 {%0,%1,%2,%3}, [%4];" \
        : "=r"(r0),"=r"(r1),"=r"(r2),"=r"(r3) : "r"(a))

#define MMA16816(c,a,b0,b1) \
    asm volatile("mma.sync.aligned.m16n8k16.row.col.f32.bf16.bf16.f32 " \
        "{%0,%1,%2,%3}, {%4,%5,%6,%7}, {%8,%9}, {%0,%1,%2,%3};" \
        : "+f"((c)[0]),"+f"((c)[1]),"+f"((c)[2]),"+f"((c)[3]) \
        : "r"((a)[0]),"r"((a)[1]),"r"((a)[2]),"r"((a)[3]), "r"(b0),"r"(b1))

// ---------------- mma.sync split-bf16 GEMM ----------------
// C[M,N] = act(A@B^T + bias)(+resid); A:[M,K] hi/lo bf16, B:[N,K] hi/lo bf16.
// BM=128, BN=128, BK=64, 3-stage cp.async pipeline, 8 warps (2m x 4n), warp tile 64x32.
#define BM 128
#define BN 128
#define STG 65536                    // per-stage: Ah 16K | Al 16K | Bh 16K | Bl 16K
#define GEMM_SMEM (3*STG)            // 196608
#define PSTG 3

template<int ACT, int OUTBF>
__global__ __launch_bounds__(256, 1)
void tcgemm(const bf16* __restrict__ Ah, const bf16* __restrict__ Al,
            const bf16* __restrict__ Bh, const bf16* __restrict__ Bl,
            const float* __restrict__ bias,
            float* __restrict__ C, bf16* __restrict__ Ch, bf16* __restrict__ Cl,
            const float* __restrict__ resid, const int* __restrict__ rowmap,
            int M, int N, int K)
{
    extern __shared__ char smem[];
    uint32_t sb = s2u(smem);
    int tid = threadIdx.x, lane = tid&31, wid = tid>>5;
    int wm = wid&1, wn = wid>>1;
    int m0 = blockIdx.y*BM, n0 = blockIdx.x*BN;

    // ---- loader address precompute (chunk-invariant) ----
    size_t aOff[4]; uint32_t aSw[4];
    size_t bOff[4]; uint32_t bSw[4];
    #pragma unroll
    for (int i=0;i<4;++i){
        int t = tid+256*i, r = t>>3, c = t&7;
        int am = m0+r; if (am > M-1) am = M-1;
        int ar = rowmap ? rowmap[am] : am;
        aOff[i] = (size_t)ar*K + c*8;
        uint32_t o = r*128 + c*16;
        aSw[i] = SWZ(o);
        bOff[i] = (size_t)(n0+r)*K + c*8;
        bSw[i] = SWZ(o);
    }

    const int NC = K/64;
    #define LOAD_STAGE(s_, ck_) do { \
        uint32_t aH_ = sb + (s_)*STG, aL_ = aH_ + 16384; \
        uint32_t bH_ = aH_ + 32768,  bL_ = aH_ + 49152; \
        size_t ko_ = (size_t)(ck_)*64; \
        _Pragma("unroll") \
        for (int i=0;i<4;++i){ cp16(aH_+aSw[i], Ah+aOff[i]+ko_); cp16(aL_+aSw[i], Al+aOff[i]+ko_); } \
        _Pragma("unroll") \
        for (int i=0;i<4;++i){ cp16(bH_+bSw[i], Bh+bOff[i]+ko_); cp16(bL_+bSw[i], Bl+bOff[i]+ko_); } \
    } while(0)

    LOAD_STAGE(0, 0); CP_COMMIT();
    LOAD_STAGE(1, 1); CP_COMMIT();

    // ---- per-lane ldmatrix row/col precompute ----
    int rA  = wm*64 + (lane&15);            // + mi*16
    int kbA = (lane>>4)*16;                 // + ks*32
    int rB  = wn*32 + (lane&7) + ((lane>>4)<<3);  // + ng*16
    int kbB = ((lane>>3)&1)*16;             // + ks*32

    float acc[4][4][4];
    #pragma unroll
    for (int i=0;i<4;++i)
        #pragma unroll
        for (int j=0;j<4;++j)
            #pragma unroll
            for (int r=0;r<4;++r) acc[i][j][r]=0.f;

    for (int ck=0; ck<NC; ++ck){
        CP_WAIT1();
        __syncthreads();
        int s = ck % PSTG;
        uint32_t uaH = sb + s*STG, uaL = uaH + 16384;
        uint32_t ubH = uaH + 32768, ubL = uaH + 49152;
        #pragma unroll
        for (int ks=0; ks<4; ++ks){
            uint32_t ah[4][4], al[4][4], bh[2][4], bl[2][4];
            #pragma unroll
            for (int mi=0;mi<4;++mi){
                uint32_t o = ((uint32_t)(rA + mi*16)<<7) + ks*32 + kbA;
                o = SWZ(o);
                LDM4(ah[mi][0],ah[mi][1],ah[mi][2],ah[mi][3], uaH + o);
                LDM4(al[mi][0],al[mi][1],al[mi][2],al[mi][3], uaL + o);
            }
            #pragma unroll
            for (int ng=0;ng<2;++ng){
                uint32_t o = ((uint32_t)(rB + ng*16)<<7) + ks*32 + kbB;
                o = SWZ(o);
                LDM4(bh[ng][0],bh[ng][1],bh[ng][2],bh[ng][3], ubH + o);
                LDM4(bl[ng][0],bl[ng][1],bl[ng][2],bl[ng][3], ubL + o);
            }
            #pragma unroll
            for (int mi=0;mi<4;++mi)
                #pragma unroll
                for (int nj=0;nj<4;++nj){
                    int ng = nj>>1, f = (nj&1)*2;
                    MMA16816(acc[mi][nj], ah[mi], bh[ng][f], bh[ng][f+1]);
                    MMA16816(acc[mi][nj], ah[mi], bl[ng][f], bl[ng][f+1]);
                    MMA16816(acc[mi][nj], al[mi], bh[ng][f], bh[ng][f+1]);
                }
        }
        __syncthreads();
        int nk = ck + 2;
        if (nk < NC) LOAD_STAGE(nk % PSTG, nk);
        CP_COMMIT();
    }

    // ---- epilogue ----
    int g = lane>>2, tg = lane&3;
    #pragma unroll
    for (int mi=0;mi<4;++mi){
        #pragma unroll
        for (int half=0; half<2; ++half){
            int m = m0 + wm*64 + mi*16 + g + half*8;
            if (m < M){
                #pragma unroll
                for (int nj=0;nj<4;++nj){
                    int n = n0 + wn*32 + nj*8 + tg*2;
                    float v0 = acc[mi][nj][half*2+0] + __ldg(bias+n);
                    float v1 = acc[mi][nj][half*2+1] + __ldg(bias+n+1);
                    if (ACT==1){
                        v0 = 0.5f*v0*(1.0f+erff(v0*0.70710678118654752f));
                        v1 = 0.5f*v1*(1.0f+erff(v1*0.70710678118654752f));
                    }
                    if (ACT==2){ v0 = fmaxf(v0,0.f); v1 = fmaxf(v1,0.f); }
                    if (resid){
                        float2 rr = *(const float2*)(resid + (size_t)m*N + n);
                        v0 += rr.x; v1 += rr.y;
                    }
                    if (OUTBF==0){
                        float2 w; w.x=v0; w.y=v1;
                        *(float2*)(C + (size_t)m*N + n) = w;
                    } else {
                        bf16 h0=__float2bfloat16(v0), h1=__float2bfloat16(v1);
                        __nv_bfloat162 H; H.x=h0; H.y=h1;
                        __nv_bfloat162 L;
                        L.x=__float2bfloat16(v0-__bfloat162float(h0));
                        L.y=__float2bfloat16(v1-__bfloat162float(h1));
                        *(__nv_bfloat162*)(Ch + (size_t)m*N + n) = H;
                        *(__nv_bfloat162*)(Cl + (size_t)m*N + n) = L;
                    }
                }
            }
        }
    }
}

// ---------------- weight transpose + split ----------------
__global__ void convert_wT(const float* __restrict__ W, bf16* __restrict__ Wh,
                           bf16* __restrict__ Wl, int K, int N)
{
    __shared__ float t[32][33];
    size_t mo = (size_t)blockIdx.z*K*N;
    int n0 = blockIdx.x*32, k0 = blockIdx.y*32;
    int tx = threadIdx.x, ty = threadIdx.y;
    #pragma unroll
    for (int i=0;i<4;++i)
        t[ty+8*i][tx] = W[mo + (size_t)(k0+ty+8*i)*N + n0+tx];
    __syncthreads();
    #pragma unroll
    for (int i=0;i<4;++i){
        float v = t[tx][ty+8*i];
        size_t o = mo + (size_t)(n0+ty+8*i)*K + k0+tx;
        bf16 h = __float2bfloat16(v);
        Wh[o] = h;
        Wl[o] = __float2bfloat16(v - __bfloat162float(h));
    }
}

__global__ void pack_bqkv(const float* bq, const float* bk, const float* bv)
{
    int t = blockIdx.x*blockDim.x + threadIdx.x;
    if (t < LL*DDIM){
        int l = t/DDIM, d = t%DDIM;
        g_bqkv[(size_t)l*3*DDIM + d] = bq[t];
        g_bqkv[(size_t)l*3*DDIM + DDIM + d] = bk[t];
        g_bqkv[(size_t)l*3*DDIM + 2*DDIM + d] = bv[t];
    }
}

// ---------------- embed ----------------
__global__ void embed_kernel(const int* __restrict__ tokens, const float* __restrict__ pos_emb,
                             const float* __restrict__ emb_obs, const float* __restrict__ emb_act,
                             float* __restrict__ x)
{
    int row = blockIdx.x, s = row % SS;
    int tok = tokens[row];
    bool is_obs = (s % TPB_) < (TPB_-1);
    const float* e = is_obs ? (emb_obs + (size_t)min(tok,VOBS_-1)*DDIM)
                            : (emb_act + (size_t)min(tok,VACT_-1)*DDIM);
    const float* pe = pos_emb + (size_t)s*DDIM;
    float* xo = x + (size_t)row*DDIM;
    for (int d = threadIdx.x; d < DDIM; d += blockDim.x) xo[d] = e[d] + pe[d];
}

// ---------------- LN -> split bf16 ----------------
__device__ __forceinline__ float bsum256(float v)
{
    __shared__ float sh[8];
    int ln = threadIdx.x&31, w = threadIdx.x>>5;
    #pragma unroll
    for (int o=16;o>0;o>>=1) v += __shfl_xor_sync(0xffffffffu, v, o);
    if (ln==0) sh[w]=v;
    __syncthreads();
    if (w==0){
        float t = (ln<8)?sh[ln]:0.f;
        #pragma unroll
        for (int o=4;o>0;o>>=1) t += __shfl_xor_sync(0xffffffffu, t, o);
        if (ln==0) sh[0]=t;
    }
    __syncthreads();
    float r = sh[0];
    __syncthreads();
    return r;
}

__global__ void ln_kernel(const float* __restrict__ x, const float* __restrict__ g,
                          const float* __restrict__ b, bf16* __restrict__ oh, bf16* __restrict__ ol)
{
    int row = blockIdx.x, t = threadIdx.x;
    const float* xr = x + (size_t)row*DDIM;
    float v[4]; float s = 0.f;
    #pragma unroll
    for (int i=0;i<4;++i){ v[i]=xr[t+256*i]; s+=v[i]; }
    float mean = bsum256(s) * (1.f/DDIM);
    float q = 0.f;
    #pragma unroll
    for (int i=0;i<4;++i){ float d=v[i]-mean; q+=d*d; }
    float rstd = rsqrtf(bsum256(q)*(1.f/DDIM) + 1e-3f);
    #pragma unroll
    for (int i=0;i<4;++i){
        int idx = t+256*i;
        float y = (v[i]-mean)*rstd*g[idx] + b[idx];
        bf16 h = __float2bfloat16(y);
        oh[(size_t)row*DDIM+idx] = h;
        ol[(size_t)row*DDIM+idx] = __float2bfloat16(y-__bfloat162float(h));
    }
}

// ---------------- attention (qkv packed fp32) -> split bf16 o ----------------
__global__ void attn_kernel(const float* __restrict__ qkv,
                            bf16* __restrict__ o_hi, bf16* __restrict__ o_lo)
{
    const int RS = 3*DDIM;
    int bh = blockIdx.y, b = bh>>4, h = bh&15;
    int qt = blockIdx.x, tid = threadIdx.x;
    int i = qt*64 + tid;
    bool valid = i < SS;
    int irow = valid ? i : SS-1;
    size_t rb = (size_t)b*SS;

    float qreg[64];
    {
        const float4* q4 = (const float4*)(qkv + (rb+irow)*RS + h*DH);
        #pragma unroll
        for (int d=0;d<16;++d){
            float4 t = q4[d];
            qreg[4*d]=t.x; qreg[4*d+1]=t.y; qreg[4*d+2]=t.z; qreg[4*d+3]=t.w;
        }
    }
    __shared__ float4 Ksh[64][16];
    __shared__ float4 Vsh[64][16];
    float oacc[64];
    #pragma unroll
    for (int d=0;d<64;++d) oacc[d]=0.f;
    float m = -1e30f, l = 0.f;
    const float scale = 0.125f;

    for (int kt=0; kt<=qt; ++kt){
        int j0 = kt*64, nk = min(64, SS-j0);
        __syncthreads();
        #pragma unroll
        for (int it=0;it<16;++it){
            int idx = it*64+tid, j = idx>>4, d4 = idx&15;
            if (j < nk){
                Ksh[j][d4] = *(const float4*)(qkv + (rb+j0+j)*RS + DDIM + h*DH + 4*d4);
                Vsh[j][d4] = *(const float4*)(qkv + (rb+j0+j)*RS + 2*DDIM + h*DH + 4*d4);
            }
        }
        __syncthreads();
        if (valid){
            const float* Ks = (const float*)Ksh;
            const float* Vs = (const float*)Vsh;
            int je = min(nk, i-j0+1);
            for (int j=0;j<je;++j){
                const float* kr = Ks + j*64;
                float s = 0.f;
                #pragma unroll
                for (int d=0;d<64;++d) s = fmaf(qreg[d], kr[d], s);
                s *= scale;
                const float* vr = Vs + j*64;
                if (s > m){
                    float c = __expf(m-s);
                    l = l*c + 1.f;
                    #pragma unroll
                    for (int d=0;d<64;++d) oacc[d] = fmaf(oacc[d], c, vr[d]);
                    m = s;
                } else {
                    float p = __expf(s-m);
                    l += p;
                    #pragma unroll
                    for (int d=0;d<64;++d) oacc[d] = fmaf(p, vr[d], oacc[d]);
                }
            }
        }
    }
    if (valid){
        float inv = 1.f/l;
        size_t ob = (rb+irow)*DDIM + h*DH;
        #pragma unroll
        for (int d=0;d<64;++d){
            float val = oacc[d]*inv;
            bf16 hh = __float2bfloat16(val);
            o_hi[ob+d] = hh;
            o_lo[ob+d] = __float2bfloat16(val-__bfloat162float(hh));
        }
    }
}

// ---------------- misc ----------------
__global__ void build_idx_kernel()
{
    int t = blockIdx.x*blockDim.x + threadIdx.x;
    if (t < NOBS){
        int b = t/960, j = t%960, blk = j/16, r = j%16;
        g_obs_rows[t] = b*SS + blk*TPB_ + (r<15 ? r : 16);
    }
    if (t < NACT){
        int b = t/60, blk = t%60;
        g_act_rows[t] = b*SS + blk*TPB_ + (TPB_-1);
    }
}

__global__ void head_ends_kernel(const float* __restrict__ t2, const float* __restrict__ w,
                                 const float* __restrict__ bias, float* __restrict__ out)
{
    int r = blockIdx.x, tid = threadIdx.x;
    const float* a = t2 + (size_t)r*DDIM;
    float s0 = 0.f, s1 = 0.f;
    for (int k = tid; k < DDIM; k += 128){
        float av = a[k];
        s0 = fmaf(av, w[k*2], s0);
        s1 = fmaf(av, w[k*2+1], s1);
    }
    __shared__ float red[128];
    red[tid]=s0; __syncthreads();
    for (int st=64;st>0;st>>=1){ if (tid<st) red[tid]+=red[tid+st]; __syncthreads(); }
    if (tid==0) out[r*2] = red[0]+bias[0];
    __syncthreads();
    red[tid]=s1; __syncthreads();
    for (int st=64;st>0;st>>=1){ if (tid<st) red[tid]+=red[tid+st]; __syncthreads(); }
    if (tid==0) out[r*2+1] = red[0]+bias[1];
}

// ---------------- launch ----------------
extern "C" void kernel_launch(void* const* d_in, const int* in_sizes, int n_in,
                              void* d_out, int out_size)
{
    const int* tokens = (const int*)d_in[0];
    const float *pos_emb=(const float*)d_in[1], *emb_obs=(const float*)d_in[2], *emb_act=(const float*)d_in[3];
    const float *ln1_g=(const float*)d_in[4], *ln1_b=(const float*)d_in[5];
    const float *wq=(const float*)d_in[6], *bq=(const float*)d_in[7];
    const float *wk=(const float*)d_in[8], *bk=(const float*)d_in[9];
    const float *wv=(const float*)d_in[10], *bv=(const float*)d_in[11];
    const float *wo=(const float*)d_in[12], *bo=(const float*)d_in[13];
    const float *ln2_g=(const float*)d_in[14], *ln2_b=(const float*)d_in[15];
    const float *w1=(const float*)d_in[16], *b1=(const float*)d_in[17];
    const float *w2=(const float*)d_in[18], *b2=(const float*)d_in[19];
    const float *lnf_g=(const float*)d_in[20], *lnf_b=(const float*)d_in[21];
    const float *ho1=(const float*)d_in[22], *bo1=(const float*)d_in[23];
    const float *ho2=(const float*)d_in[24], *bo2=(const float*)d_in[25];
    const float *he1=(const float*)d_in[26], *be1=(const float*)d_in[27];
    const float *he2=(const float*)d_in[28], *be2=(const float*)d_in[29];
    float* out = (float*)d_out;

    float *x,*qkv,*t2,*bqkv;
    bf16 *h_hi,*h_lo,*o_hi,*o_lo,*mid_hi,*mid_lo,*t1_hi,*t1_lo,*wt_hi,*wt_lo;
    int *obsr,*actr;
    cudaGetSymbolAddress((void**)&x, g_x);
    cudaGetSymbolAddress((void**)&qkv, g_qkv);
    cudaGetSymbolAddress((void**)&t2, g_t2);
    cudaGetSymbolAddress((void**)&bqkv, g_bqkv);
    cudaGetSymbolAddress((void**)&h_hi, g_h_hi);
    cudaGetSymbolAddress((void**)&h_lo, g_h_lo);
    cudaGetSymbolAddress((void**)&o_hi, g_o_hi);
    cudaGetSymbolAddress((void**)&o_lo, g_o_lo);
    cudaGetSymbolAddress((void**)&mid_hi, g_mid_hi);
    cudaGetSymbolAddress((void**)&mid_lo, g_mid_lo);
    cudaGetSymbolAddress((void**)&t1_hi, g_t1_hi);
    cudaGetSymbolAddress((void**)&t1_lo, g_t1_lo);
    cudaGetSymbolAddress((void**)&wt_hi, g_wt_hi);
    cudaGetSymbolAddress((void**)&wt_lo, g_wt_lo);
    cudaGetSymbolAddress((void**)&obsr, g_obs_rows);
    cudaGetSymbolAddress((void**)&actr, g_act_rows);

    cudaFuncSetAttribute(tcgemm<0,0>, cudaFuncAttributeMaxDynamicSharedMemorySize, GEMM_SMEM);
    cudaFuncSetAttribute(tcgemm<1,1>, cudaFuncAttributeMaxDynamicSharedMemorySize, GEMM_SMEM);
    cudaFuncSetAttribute(tcgemm<2,1>, cudaFuncAttributeMaxDynamicSharedMemorySize, GEMM_SMEM);
    cudaFuncSetAttribute(tcgemm<2,0>, cudaFuncAttributeMaxDynamicSharedMemorySize, GEMM_SMEM);

    dim3 cb(32,8);
    for (int part = 0; part < 3; ++part){
        const float* src = part==0 ? wq : (part==1 ? wk : wv);
        for (int l = 0; l < LL; ++l){
            size_t oo = (size_t)WQKV_OFF + (size_t)l*3*DDIM*DDIM + (size_t)part*DDIM*DDIM;
            convert_wT<<<dim3(DDIM/32, DDIM/32, 1), cb>>>(src + (size_t)l*DDIM*DDIM, wt_hi+oo, wt_lo+oo, DDIM, DDIM);
        }
    }
    convert_wT<<<dim3(DDIM/32, DDIM/32, LL), cb>>>(wo, wt_hi+WO_OFF, wt_lo+WO_OFF, DDIM, DDIM);
    convert_wT<<<dim3(FF/32, DDIM/32, LL), cb>>>(w1, wt_hi+W1_OFF, wt_lo+W1_OFF, DDIM, FF);
    convert_wT<<<dim3(DDIM/32, FF/32, LL), cb>>>(w2, wt_hi+W2_OFF, wt_lo+W2_OFF, FF, DDIM);
    convert_wT<<<dim3(DDIM/32, DDIM/32, 1), cb>>>(ho1, wt_hi+HO1_OFF, wt_lo+HO1_OFF, DDIM, DDIM);
    convert_wT<<<dim3(VOBS_/32, DDIM/32, 1), cb>>>(ho2, wt_hi+HO2_OFF, wt_lo+HO2_OFF, DDIM, VOBS_);
    convert_wT<<<dim3(DDIM/32, DDIM/32, 1), cb>>>(he1, wt_hi+HE1_OFF, wt_lo+HE1_OFF, DDIM, DDIM);
    pack_bqkv<<<(LL*DDIM+255)/256, 256>>>(bq, bk, bv);
    build_idx_kernel<<<(NOBS+255)/256, 256>>>();

    embed_kernel<<<NTOK, 256>>>(tokens, pos_emb, emb_obs, emb_act, x);

    #define GG(M_, N_) dim3((N_)/BN, ((M_)+BM-1)/BM)
    for (int l = 0; l < LL; ++l){
        size_t dd = (size_t)l*DDIM*DDIM;
        ln_kernel<<<NTOK, 256>>>(x, ln1_g+l*DDIM, ln1_b+l*DDIM, h_hi, h_lo);
        tcgemm<0,0><<<GG(NTOK, 3*DDIM), 256, GEMM_SMEM>>>(
            h_hi, h_lo, wt_hi+WQKV_OFF+(size_t)l*3*DDIM*DDIM, wt_lo+WQKV_OFF+(size_t)l*3*DDIM*DDIM,
            bqkv+(size_t)l*3*DDIM, qkv, nullptr, nullptr, nullptr, nullptr, NTOK, 3*DDIM, DDIM);
        attn_kernel<<<dim3((SS+63)/64, BB*HH), 64>>>(qkv, o_hi, o_lo);
        tcgemm<0,0><<<GG(NTOK, DDIM), 256, GEMM_SMEM>>>(
            o_hi, o_lo, wt_hi+WO_OFF+dd, wt_lo+WO_OFF+dd,
            bo+l*DDIM, x, nullptr, nullptr, x, nullptr, NTOK, DDIM, DDIM);
        ln_kernel<<<NTOK, 256>>>(x, ln2_g+l*DDIM, ln2_b+l*DDIM, h_hi, h_lo);
        tcgemm<1,1><<<GG(NTOK, FF), 256, GEMM_SMEM>>>(
            h_hi, h_lo, wt_hi+W1_OFF+(size_t)l*FF*DDIM, wt_lo+W1_OFF+(size_t)l*FF*DDIM,
            b1+(size_t)l*FF, nullptr, mid_hi, mid_lo, nullptr, nullptr, NTOK, FF, DDIM);
        tcgemm<0,0><<<GG(NTOK, DDIM), 256, GEMM_SMEM>>>(
            mid_hi, mid_lo, wt_hi+W2_OFF+(size_t)l*DDIM*FF, wt_lo+W2_OFF+(size_t)l*DDIM*FF,
            b2+l*DDIM, x, nullptr, nullptr, x, nullptr, NTOK, DDIM, FF);
    }

    ln_kernel<<<NTOK, 256>>>(x, lnf_g, lnf_b, h_hi, h_lo);

    tcgemm<2,1><<<GG(NOBS, DDIM), 256, GEMM_SMEM>>>(
        h_hi, h_lo, wt_hi+HO1_OFF, wt_lo+HO1_OFF, bo1,
        nullptr, t1_hi, t1_lo, nullptr, obsr, NOBS, DDIM, DDIM);
    tcgemm<0,0><<<GG(NOBS, VOBS_), 256, GEMM_SMEM>>>(
        t1_hi, t1_lo, wt_hi+HO2_OFF, wt_lo+HO2_OFF, bo2,
        out, nullptr, nullptr, nullptr, nullptr, NOBS, VOBS_, DDIM);

    tcgemm<2,0><<<GG(NACT, DDIM), 256, GEMM_SMEM>>>(
        h_hi, h_lo, wt_hi+HE1_OFF, wt_lo+HE1_OFF, be1,
        t2, nullptr, nullptr, nullptr, actr, NACT, DDIM, DDIM);
    head_ends_kernel<<<NACT, 128>>>(t2, he2, be2, out + (size_t)NOBS*VOBS_);
}

// round 5
// speedup vs baseline: 2.5362x; 1.0150x over previous
#include <cuda_runtime.h>
#include <cuda_bf16.h>
#include <math.h>
#include <stdint.h>

typedef __nv_bfloat16 bf16;

#define BB 4
#define SS 1020
#define DDIM 1024
#define HH 16
#define DH 64
#define LL 4
#define TPB_ 17
#define FF 4096
#define NTOK (BB*SS)
#define NOBS (BB*960)
#define NACT (BB*60)
#define VOBS_ 4096
#define VACT_ 16

// ---------------- static scratch ----------------
__device__ __align__(256) float g_x[NTOK*DDIM];
__device__ __align__(256) float g_qkv[NTOK*3*DDIM];
__device__ __align__(256) float g_t2[NACT*DDIM];
__device__ __align__(256) bf16 g_h_hi[NTOK*DDIM];
__device__ __align__(256) bf16 g_h_lo[NTOK*DDIM];
__device__ __align__(256) bf16 g_o_hi[NTOK*DDIM];
__device__ __align__(256) bf16 g_o_lo[NTOK*DDIM];
__device__ __align__(256) bf16 g_mid_hi[NTOK*FF];
__device__ __align__(256) bf16 g_mid_lo[NTOK*FF];
__device__ __align__(256) bf16 g_t1_hi[NOBS*DDIM];
__device__ __align__(256) bf16 g_t1_lo[NOBS*DDIM];
__device__ float g_bqkv[LL*3*DDIM];
__device__ int g_obs_rows[NOBS];
__device__ int g_act_rows[NACT];

#define WQKV_OFF 0
#define WO_OFF  (WQKV_OFF + LL*3*DDIM*DDIM)
#define W1_OFF  (WO_OFF + LL*DDIM*DDIM)
#define W2_OFF  (W1_OFF + LL*FF*DDIM)
#define HO1_OFF (W2_OFF + LL*DDIM*FF)
#define HO2_OFF (HO1_OFF + DDIM*DDIM)
#define HE1_OFF (HO2_OFF + VOBS_*DDIM)
#define WT_TOT  (HE1_OFF + DDIM*DDIM)
__device__ __align__(256) bf16 g_wt_hi[WT_TOT];
__device__ __align__(256) bf16 g_wt_lo[WT_TOT];

// ---------------- PTX helpers ----------------
__device__ __forceinline__ uint32_t s2u(const void* p){ return (uint32_t)__cvta_generic_to_shared(p); }
__device__ __forceinline__ void cp16(uint32_t d, const void* s){
    asm volatile("cp.async.cg.shared.global [%0], [%1], 16;\n"::"r"(d),"l"(s));
}
#define CP_COMMIT() asm volatile("cp.async.commit_group;\n":::"memory")
#define CP_WAIT1()  asm volatile("cp.async.wait_group 1;\n":::"memory")
#define CP_WAIT0()  asm volatile("cp.async.wait_group 0;\n":::"memory")

#define SWZ(o) ((o) ^ (((o)>>3)&0x70))

#define LDM4(r0,r1,r2,r3,a) \
    asm volatile("ldmatrix.sync.aligned.m8n8.x4.shared.b16 {%0,%1,%2,%3}, [%4];" \
        : "=r"(r0),"=r"(r1),"=r"(r2),"=r"(r3) : "r"(a))

#define MMA16816(c,a,b0,b1) \
    asm volatile("mma.sync.aligned.m16n8k16.row.col.f32.bf16.bf16.f32 " \
        "{%0,%1,%2,%3}, {%4,%5,%6,%7}, {%8,%9}, {%0,%1,%2,%3};" \
        : "+f"((c)[0]),"+f"((c)[1]),"+f"((c)[2]),"+f"((c)[3]) \
        : "r"((a)[0]),"r"((a)[1]),"r"((a)[2]),"r"((a)[3]), "r"(b0),"r"(b1))

// ---------------- mma.sync split-bf16 GEMM ----------------
// BM=128, BN=256, BK=64, 2-stage cp.async pipeline, 8 warps (2m x 4n), warp tile 64x64.
#define BM 128
#define BN 256
#define STG 98304   // Ah 16K | Al 16K | Bh 32K | Bl 32K
#define GEMM_SMEM (2*STG)

template<int ACT, int OUTBF>
__global__ __launch_bounds__(256, 1)
void tcgemm(const bf16* __restrict__ Ah, const bf16* __restrict__ Al,
            const bf16* __restrict__ Bh, const bf16* __restrict__ Bl,
            const float* __restrict__ bias,
            float* __restrict__ C, bf16* __restrict__ Ch, bf16* __restrict__ Cl,
            const float* __restrict__ resid, const int* __restrict__ rowmap,
            int M, int N, int K)
{
    extern __shared__ char smem[];
    uint32_t sb = s2u(smem);
    int tid = threadIdx.x, lane = tid&31, wid = tid>>5;
    int wm = wid&1, wn = wid>>1;          // 2 x 4 warp grid
    int m0 = blockIdx.y*BM, n0 = blockIdx.x*BN;

    size_t aOff[4]; uint32_t aSw[4];
    #pragma unroll
    for (int i=0;i<4;++i){
        int t = tid+256*i, r = t>>3, c = t&7;   // 128 rows x 8 float4
        int am = m0+r; if (am > M-1) am = M-1;
        int ar = rowmap ? rowmap[am] : am;
        aOff[i] = (size_t)ar*K + c*8;
        uint32_t o = r*128 + c*16;
        aSw[i] = SWZ(o);
    }
    size_t bOff[8]; uint32_t bSw[8];
    #pragma unroll
    for (int i=0;i<8;++i){
        int t = tid+256*i, r = t>>3, c = t&7;   // 256 rows x 8 float4
        bOff[i] = (size_t)(n0+r)*K + c*8;
        uint32_t o = r*128 + c*16;
        bSw[i] = SWZ(o);
    }

    const int NC = K/64;
    #define LOAD_STAGE(s_, ck_) do { \
        uint32_t aH_ = sb + (s_)*STG, aL_ = aH_ + 16384; \
        uint32_t bH_ = aH_ + 32768,  bL_ = aH_ + 65536; \
        size_t ko_ = (size_t)(ck_)*64; \
        _Pragma("unroll") \
        for (int i=0;i<4;++i){ cp16(aH_+aSw[i], Ah+aOff[i]+ko_); cp16(aL_+aSw[i], Al+aOff[i]+ko_); } \
        _Pragma("unroll") \
        for (int i=0;i<8;++i){ cp16(bH_+bSw[i], Bh+bOff[i]+ko_); cp16(bL_+bSw[i], Bl+bOff[i]+ko_); } \
    } while(0)

    LOAD_STAGE(0, 0); CP_COMMIT();

    int rA  = wm*64 + (lane&15);
    int kbA = (lane>>4)*16;
    int rB  = wn*64 + (lane&7) + ((lane>>4)<<3);
    int kbB = ((lane>>3)&1)*16;

    float acc[4][8][4];
    #pragma unroll
    for (int i=0;i<4;++i)
        #pragma unroll
        for (int j=0;j<8;++j)
            #pragma unroll
            for (int r=0;r<4;++r) acc[i][j][r]=0.f;

    for (int ck=0; ck<NC; ++ck){
        if (ck+1 < NC){ LOAD_STAGE((ck+1)&1, ck+1); CP_COMMIT(); CP_WAIT1(); }
        else CP_WAIT0();
        __syncthreads();
        int s = ck & 1;
        uint32_t uaH = sb + s*STG, uaL = uaH + 16384;
        uint32_t ubH = uaH + 32768, ubL = uaH + 65536;
        #pragma unroll
        for (int ks=0; ks<4; ++ks){
            uint32_t ah[4][4], al[4][4];
            #pragma unroll
            for (int mi=0;mi<4;++mi){
                uint32_t o = ((uint32_t)(rA + mi*16)<<7) + ks*32 + kbA;
                o = SWZ(o);
                LDM4(ah[mi][0],ah[mi][1],ah[mi][2],ah[mi][3], uaH + o);
                LDM4(al[mi][0],al[mi][1],al[mi][2],al[mi][3], uaL + o);
            }
            #pragma unroll
            for (int ng=0;ng<4;++ng){
                uint32_t bh[4], bl[4];
                uint32_t o = ((uint32_t)(rB + ng*16)<<7) + ks*32 + kbB;
                o = SWZ(o);
                LDM4(bh[0],bh[1],bh[2],bh[3], ubH + o);
                LDM4(bl[0],bl[1],bl[2],bl[3], ubL + o);
                #pragma unroll
                for (int mi=0;mi<4;++mi){
                    #pragma unroll
                    for (int j=0;j<2;++j){
                        MMA16816(acc[mi][ng*2+j], ah[mi], bh[j*2], bh[j*2+1]);
                        MMA16816(acc[mi][ng*2+j], ah[mi], bl[j*2], bl[j*2+1]);
                        MMA16816(acc[mi][ng*2+j], al[mi], bh[j*2], bh[j*2+1]);
                    }
                }
            }
        }
        __syncthreads();
    }

    // ---- epilogue ----
    int g = lane>>2, tg = lane&3;
    #pragma unroll
    for (int mi=0;mi<4;++mi){
        #pragma unroll
        for (int half=0; half<2; ++half){
            int m = m0 + wm*64 + mi*16 + g + half*8;
            if (m < M){
                #pragma unroll
                for (int nj=0;nj<8;++nj){
                    int n = n0 + wn*64 + nj*8 + tg*2;
                    float v0 = acc[mi][nj][half*2+0] + __ldg(bias+n);
                    float v1 = acc[mi][nj][half*2+1] + __ldg(bias+n+1);
                    if (ACT==1){
                        v0 = 0.5f*v0*(1.0f+erff(v0*0.70710678118654752f));
                        v1 = 0.5f*v1*(1.0f+erff(v1*0.70710678118654752f));
                    }
                    if (ACT==2){ v0 = fmaxf(v0,0.f); v1 = fmaxf(v1,0.f); }
                    if (resid){
                        float2 rr = *(const float2*)(resid + (size_t)m*N + n);
                        v0 += rr.x; v1 += rr.y;
                    }
                    if (OUTBF==0){
                        float2 w; w.x=v0; w.y=v1;
                        *(float2*)(C + (size_t)m*N + n) = w;
                    } else {
                        bf16 h0=__float2bfloat16(v0), h1=__float2bfloat16(v1);
                        __nv_bfloat162 H; H.x=h0; H.y=h1;
                        __nv_bfloat162 L;
                        L.x=__float2bfloat16(v0-__bfloat162float(h0));
                        L.y=__float2bfloat16(v1-__bfloat162float(h1));
                        *(__nv_bfloat162*)(Ch + (size_t)m*N + n) = H;
                        *(__nv_bfloat162*)(Cl + (size_t)m*N + n) = L;
                    }
                }
            }
        }
    }
}

// ---------------- weight transpose + split (coalesced both sides) ----------------
// tile: 64 k-rows x 32 n-cols; out [N,K]; block (32,8)
__global__ void convert_wT(const float* __restrict__ W, bf16* __restrict__ Wh,
                           bf16* __restrict__ Wl, int K, int N,
                           long inMS, long outMS)
{
    __shared__ float t[64][33];
    const float* Wm = W + (size_t)blockIdx.z*inMS;
    bf16* Whm = Wh + (size_t)blockIdx.z*outMS;
    bf16* Wlm = Wl + (size_t)blockIdx.z*outMS;
    int n0 = blockIdx.x*32, k0 = blockIdx.y*64;
    int tx = threadIdx.x, ty = threadIdx.y;
    #pragma unroll
    for (int i=0;i<8;++i)
        t[ty+8*i][tx] = Wm[(size_t)(k0+ty+8*i)*N + n0+tx];
    __syncthreads();
    #pragma unroll
    for (int i=0;i<4;++i){
        int nn = ty + 8*i;
        float v0 = t[tx*2][nn], v1 = t[tx*2+1][nn];
        bf16 h0 = __float2bfloat16(v0), h1 = __float2bfloat16(v1);
        __nv_bfloat162 H; H.x=h0; H.y=h1;
        __nv_bfloat162 L;
        L.x = __float2bfloat16(v0-__bfloat162float(h0));
        L.y = __float2bfloat16(v1-__bfloat162float(h1));
        size_t o = (size_t)(n0+nn)*K + k0 + tx*2;
        *(__nv_bfloat162*)(Whm+o) = H;
        *(__nv_bfloat162*)(Wlm+o) = L;
    }
}

__global__ void pack_bqkv(const float* bq, const float* bk, const float* bv)
{
    int t = blockIdx.x*blockDim.x + threadIdx.x;
    if (t < LL*DDIM){
        int l = t/DDIM, d = t%DDIM;
        g_bqkv[(size_t)l*3*DDIM + d] = bq[t];
        g_bqkv[(size_t)l*3*DDIM + DDIM + d] = bk[t];
        g_bqkv[(size_t)l*3*DDIM + 2*DDIM + d] = bv[t];
    }
}

// ---------------- embed ----------------
__global__ void embed_kernel(const int* __restrict__ tokens, const float* __restrict__ pos_emb,
                             const float* __restrict__ emb_obs, const float* __restrict__ emb_act,
                             float* __restrict__ x)
{
    int row = blockIdx.x, s = row % SS;
    int tok = tokens[row];
    bool is_obs = (s % TPB_) < (TPB_-1);
    const float* e = is_obs ? (emb_obs + (size_t)min(tok,VOBS_-1)*DDIM)
                            : (emb_act + (size_t)min(tok,VACT_-1)*DDIM);
    const float* pe = pos_emb + (size_t)s*DDIM;
    float* xo = x + (size_t)row*DDIM;
    for (int d = threadIdx.x; d < DDIM; d += blockDim.x) xo[d] = e[d] + pe[d];
}

// ---------------- LN -> split bf16 ----------------
__device__ __forceinline__ float bsum256(float v)
{
    __shared__ float sh[8];
    int ln = threadIdx.x&31, w = threadIdx.x>>5;
    #pragma unroll
    for (int o=16;o>0;o>>=1) v += __shfl_xor_sync(0xffffffffu, v, o);
    if (ln==0) sh[w]=v;
    __syncthreads();
    if (w==0){
        float t = (ln<8)?sh[ln]:0.f;
        #pragma unroll
        for (int o=4;o>0;o>>=1) t += __shfl_xor_sync(0xffffffffu, t, o);
        if (ln==0) sh[0]=t;
    }
    __syncthreads();
    float r = sh[0];
    __syncthreads();
    return r;
}

__global__ void ln_kernel(const float* __restrict__ x, const float* __restrict__ g,
                          const float* __restrict__ b, bf16* __restrict__ oh, bf16* __restrict__ ol)
{
    int row = blockIdx.x, t = threadIdx.x;
    const float* xr = x + (size_t)row*DDIM;
    float v[4]; float s = 0.f;
    #pragma unroll
    for (int i=0;i<4;++i){ v[i]=xr[t+256*i]; s+=v[i]; }
    float mean = bsum256(s) * (1.f/DDIM);
    float q = 0.f;
    #pragma unroll
    for (int i=0;i<4;++i){ float d=v[i]-mean; q+=d*d; }
    float rstd = rsqrtf(bsum256(q)*(1.f/DDIM) + 1e-3f);
    #pragma unroll
    for (int i=0;i<4;++i){
        int idx = t+256*i;
        float y = (v[i]-mean)*rstd*g[idx] + b[idx];
        bf16 h = __float2bfloat16(y);
        oh[(size_t)row*DDIM+idx] = h;
        ol[(size_t)row*DDIM+idx] = __float2bfloat16(y-__bfloat162float(h));
    }
}

// ---------------- attention ----------------
__global__ void attn_kernel(const float* __restrict__ qkv,
                            bf16* __restrict__ o_hi, bf16* __restrict__ o_lo)
{
    const int RS = 3*DDIM;
    int bh = blockIdx.y, b = bh>>4, h = bh&15;
    int qt = blockIdx.x, tid = threadIdx.x;
    int i = qt*64 + tid;
    bool valid = i < SS;
    int irow = valid ? i : SS-1;
    size_t rb = (size_t)b*SS;

    float qreg[64];
    {
        const float4* q4 = (const float4*)(qkv + (rb+irow)*RS + h*DH);
        #pragma unroll
        for (int d=0;d<16;++d){
            float4 t = q4[d];
            qreg[4*d]=t.x; qreg[4*d+1]=t.y; qreg[4*d+2]=t.z; qreg[4*d+3]=t.w;
        }
    }
    __shared__ float4 Ksh[64][16];
    __shared__ float4 Vsh[64][16];
    float oacc[64];
    #pragma unroll
    for (int d=0;d<64;++d) oacc[d]=0.f;
    float m = -1e30f, l = 0.f;
    const float scale = 0.125f;

    for (int kt=0; kt<=qt; ++kt){
        int j0 = kt*64, nk = min(64, SS-j0);
        __syncthreads();
        #pragma unroll
        for (int it=0;it<16;++it){
            int idx = it*64+tid, j = idx>>4, d4 = idx&15;
            if (j < nk){
                Ksh[j][d4] = *(const float4*)(qkv + (rb+j0+j)*RS + DDIM + h*DH + 4*d4);
                Vsh[j][d4] = *(const float4*)(qkv + (rb+j0+j)*RS + 2*DDIM + h*DH + 4*d4);
            }
        }
        __syncthreads();
        if (valid){
            const float* Ks = (const float*)Ksh;
            const float* Vs = (const float*)Vsh;
            int je = min(nk, i-j0+1);
            for (int j=0;j<je;++j){
                const float* kr = Ks + j*64;
                float s = 0.f;
                #pragma unroll
                for (int d=0;d<64;++d) s = fmaf(qreg[d], kr[d], s);
                s *= scale;
                const float* vr = Vs + j*64;
                if (s > m){
                    float c = __expf(m-s);
                    l = l*c + 1.f;
                    #pragma unroll
                    for (int d=0;d<64;++d) oacc[d] = fmaf(oacc[d], c, vr[d]);
                    m = s;
                } else {
                    float p = __expf(s-m);
                    l += p;
                    #pragma unroll
                    for (int d=0;d<64;++d) oacc[d] = fmaf(p, vr[d], oacc[d]);
                }
            }
        }
    }
    if (valid){
        float inv = 1.f/l;
        size_t ob = (rb+irow)*DDIM + h*DH;
        #pragma unroll
        for (int d=0;d<64;++d){
            float val = oacc[d]*inv;
            bf16 hh = __float2bfloat16(val);
            o_hi[ob+d] = hh;
            o_lo[ob+d] = __float2bfloat16(val-__bfloat162float(hh));
        }
    }
}

// ---------------- misc ----------------
__global__ void build_idx_kernel()
{
    int t = blockIdx.x*blockDim.x + threadIdx.x;
    if (t < NOBS){
        int b = t/960, j = t%960, blk = j/16, r = j%16;
        g_obs_rows[t] = b*SS + blk*TPB_ + (r<15 ? r : 16);
    }
    if (t < NACT){
        int b = t/60, blk = t%60;
        g_act_rows[t] = b*SS + blk*TPB_ + (TPB_-1);
    }
}

__global__ void head_ends_kernel(const float* __restrict__ t2, const float* __restrict__ w,
                                 const float* __restrict__ bias, float* __restrict__ out)
{
    int r = blockIdx.x, tid = threadIdx.x;
    const float* a = t2 + (size_t)r*DDIM;
    float s0 = 0.f, s1 = 0.f;
    for (int k = tid; k < DDIM; k += 128){
        float av = a[k];
        s0 = fmaf(av, w[k*2], s0);
        s1 = fmaf(av, w[k*2+1], s1);
    }
    __shared__ float red[128];
    red[tid]=s0; __syncthreads();
    for (int st=64;st>0;st>>=1){ if (tid<st) red[tid]+=red[tid+st]; __syncthreads(); }
    if (tid==0) out[r*2] = red[0]+bias[0];
    __syncthreads();
    red[tid]=s1; __syncthreads();
    for (int st=64;st>0;st>>=1){ if (tid<st) red[tid]+=red[tid+st]; __syncthreads(); }
    if (tid==0) out[r*2+1] = red[0]+bias[1];
}

// ---------------- launch ----------------
extern "C" void kernel_launch(void* const* d_in, const int* in_sizes, int n_in,
                              void* d_out, int out_size)
{
    const int* tokens = (const int*)d_in[0];
    const float *pos_emb=(const float*)d_in[1], *emb_obs=(const float*)d_in[2], *emb_act=(const float*)d_in[3];
    const float *ln1_g=(const float*)d_in[4], *ln1_b=(const float*)d_in[5];
    const float *wq=(const float*)d_in[6], *bq=(const float*)d_in[7];
    const float *wk=(const float*)d_in[8], *bk=(const float*)d_in[9];
    const float *wv=(const float*)d_in[10], *bv=(const float*)d_in[11];
    const float *wo=(const float*)d_in[12], *bo=(const float*)d_in[13];
    const float *ln2_g=(const float*)d_in[14], *ln2_b=(const float*)d_in[15];
    const float *w1=(const float*)d_in[16], *b1=(const float*)d_in[17];
    const float *w2=(const float*)d_in[18], *b2=(const float*)d_in[19];
    const float *lnf_g=(const float*)d_in[20], *lnf_b=(const float*)d_in[21];
    const float *ho1=(const float*)d_in[22], *bo1=(const float*)d_in[23];
    const float *ho2=(const float*)d_in[24], *bo2=(const float*)d_in[25];
    const float *he1=(const float*)d_in[26], *be1=(const float*)d_in[27];
    const float *he2=(const float*)d_in[28], *be2=(const float*)d_in[29];
    float* out = (float*)d_out;

    float *x,*qkv,*t2;
    bf16 *h_hi,*h_lo,*o_hi,*o_lo,*mid_hi,*mid_lo,*t1_hi,*t1_lo,*wt_hi,*wt_lo;
    float *bqkv;
    int *obsr,*actr;
    cudaGetSymbolAddress((void**)&x, g_x);
    cudaGetSymbolAddress((void**)&qkv, g_qkv);
    cudaGetSymbolAddress((void**)&t2, g_t2);
    cudaGetSymbolAddress((void**)&bqkv, g_bqkv);
    cudaGetSymbolAddress((void**)&h_hi, g_h_hi);
    cudaGetSymbolAddress((void**)&h_lo, g_h_lo);
    cudaGetSymbolAddress((void**)&o_hi, g_o_hi);
    cudaGetSymbolAddress((void**)&o_lo, g_o_lo);
    cudaGetSymbolAddress((void**)&mid_hi, g_mid_hi);
    cudaGetSymbolAddress((void**)&mid_lo, g_mid_lo);
    cudaGetSymbolAddress((void**)&t1_hi, g_t1_hi);
    cudaGetSymbolAddress((void**)&t1_lo, g_t1_lo);
    cudaGetSymbolAddress((void**)&wt_hi, g_wt_hi);
    cudaGetSymbolAddress((void**)&wt_lo, g_wt_lo);
    cudaGetSymbolAddress((void**)&obsr, g_obs_rows);
    cudaGetSymbolAddress((void**)&actr, g_act_rows);

    cudaFuncSetAttribute(tcgemm<0,0>, cudaFuncAttributeMaxDynamicSharedMemorySize, GEMM_SMEM);
    cudaFuncSetAttribute(tcgemm<1,1>, cudaFuncAttributeMaxDynamicSharedMemorySize, GEMM_SMEM);
    cudaFuncSetAttribute(tcgemm<2,1>, cudaFuncAttributeMaxDynamicSharedMemorySize, GEMM_SMEM);
    cudaFuncSetAttribute(tcgemm<2,0>, cudaFuncAttributeMaxDynamicSharedMemorySize, GEMM_SMEM);

    dim3 cb(32,8);
    // QKV: one launch per part, z = layer. in stride D*D, out stride 3*D*D.
    for (int part = 0; part < 3; ++part){
        const float* src = part==0 ? wq : (part==1 ? wk : wv);
        convert_wT<<<dim3(DDIM/32, DDIM/64, LL), cb>>>(
            src, wt_hi+WQKV_OFF+(size_t)part*DDIM*DDIM, wt_lo+WQKV_OFF+(size_t)part*DDIM*DDIM,
            DDIM, DDIM, (long)DDIM*DDIM, (long)3*DDIM*DDIM);
    }
    convert_wT<<<dim3(DDIM/32, DDIM/64, LL), cb>>>(wo, wt_hi+WO_OFF, wt_lo+WO_OFF, DDIM, DDIM, (long)DDIM*DDIM, (long)DDIM*DDIM);
    convert_wT<<<dim3(FF/32, DDIM/64, LL), cb>>>(w1, wt_hi+W1_OFF, wt_lo+W1_OFF, DDIM, FF, (long)DDIM*FF, (long)DDIM*FF);
    convert_wT<<<dim3(DDIM/32, FF/64, LL), cb>>>(w2, wt_hi+W2_OFF, wt_lo+W2_OFF, FF, DDIM, (long)DDIM*FF, (long)DDIM*FF);
    convert_wT<<<dim3(DDIM/32, DDIM/64, 1), cb>>>(ho1, wt_hi+HO1_OFF, wt_lo+HO1_OFF, DDIM, DDIM, 0, 0);
    convert_wT<<<dim3(VOBS_/32, DDIM/64, 1), cb>>>(ho2, wt_hi+HO2_OFF, wt_lo+HO2_OFF, DDIM, VOBS_, 0, 0);
    convert_wT<<<dim3(DDIM/32, DDIM/64, 1), cb>>>(he1, wt_hi+HE1_OFF, wt_lo+HE1_OFF, DDIM, DDIM, 0, 0);
    pack_bqkv<<<(LL*DDIM+255)/256, 256>>>(bq, bk, bv);
    build_idx_kernel<<<(NOBS+255)/256, 256>>>();

    embed_kernel<<<NTOK, 256>>>(tokens, pos_emb, emb_obs, emb_act, x);

    #define GG(M_, N_) dim3((N_)/BN, ((M_)+BM-1)/BM)
    for (int l = 0; l < LL; ++l){
        size_t dd = (size_t)l*DDIM*DDIM;
        ln_kernel<<<NTOK, 256>>>(x, ln1_g+l*DDIM, ln1_b+l*DDIM, h_hi, h_lo);
        tcgemm<0,0><<<GG(NTOK, 3*DDIM), 256, GEMM_SMEM>>>(
            h_hi, h_lo, wt_hi+WQKV_OFF+(size_t)l*3*DDIM*DDIM, wt_lo+WQKV_OFF+(size_t)l*3*DDIM*DDIM,
            bqkv+(size_t)l*3*DDIM, qkv, nullptr, nullptr, nullptr, nullptr, NTOK, 3*DDIM, DDIM);
        attn_kernel<<<dim3((SS+63)/64, BB*HH), 64>>>(qkv, o_hi, o_lo);
        tcgemm<0,0><<<GG(NTOK, DDIM), 256, GEMM_SMEM>>>(
            o_hi, o_lo, wt_hi+WO_OFF+dd, wt_lo+WO_OFF+dd,
            bo+l*DDIM, x, nullptr, nullptr, x, nullptr, NTOK, DDIM, DDIM);
        ln_kernel<<<NTOK, 256>>>(x, ln2_g+l*DDIM, ln2_b+l*DDIM, h_hi, h_lo);
        tcgemm<1,1><<<GG(NTOK, FF), 256, GEMM_SMEM>>>(
            h_hi, h_lo, wt_hi+W1_OFF+(size_t)l*FF*DDIM, wt_lo+W1_OFF+(size_t)l*FF*DDIM,
            b1+(size_t)l*FF, nullptr, mid_hi, mid_lo, nullptr, nullptr, NTOK, FF, DDIM);
        tcgemm<0,0><<<GG(NTOK, DDIM), 256, GEMM_SMEM>>>(
            mid_hi, mid_lo, wt_hi+W2_OFF+(size_t)l*DDIM*FF, wt_lo+W2_OFF+(size_t)l*DDIM*FF,
            b2+l*DDIM, x, nullptr, nullptr, x, nullptr, NTOK, DDIM, FF);
    }

    ln_kernel<<<NTOK, 256>>>(x, lnf_g, lnf_b, h_hi, h_lo);

    tcgemm<2,1><<<GG(NOBS, DDIM), 256, GEMM_SMEM>>>(
        h_hi, h_lo, wt_hi+HO1_OFF, wt_lo+HO1_OFF, bo1,
        nullptr, t1_hi, t1_lo, nullptr, obsr, NOBS, DDIM, DDIM);
    tcgemm<0,0><<<GG(NOBS, VOBS_), 256, GEMM_SMEM>>>(
        t1_hi, t1_lo, wt_hi+HO2_OFF, wt_lo+HO2_OFF, bo2,
        out, nullptr, nullptr, nullptr, nullptr, NOBS, VOBS_, DDIM);

    tcgemm<2,0><<<GG(NACT, DDIM), 256, GEMM_SMEM>>>(
        h_hi, h_lo, wt_hi+HE1_OFF, wt_lo+HE1_OFF, be1,
        t2, nullptr, nullptr, nullptr, actr, NACT, DDIM, DDIM);
    head_ends_kernel<<<NACT, 128>>>(t2, he2, be2, out + (size_t)NOBS*VOBS_);
}